// round 1
// baseline (speedup 1.0000x reference)
#include <cuda_runtime.h>
#include <math.h>

#define S_LEN   4096
#define H_DIM   2048
#define NH      16
#define NKV     4
#define HD      128
#define B_BLK   64
#define T_BLK   64
#define NEG_INF (-1e9f)
#define QK_SCALE 0.08838834764831845f  /* 1/sqrt(128) */

// Scratch (allocation-free: __device__ globals)
__device__ float g_q[S_LEN * NH * HD];       // 32 MB
__device__ float g_k[S_LEN * NKV * HD];      //  8 MB
__device__ float g_v[S_LEN * NKV * HD];      //  8 MB
__device__ float g_attn[S_LEN * NH * HD];    // 32 MB

// ============================================================================
// SGEMM: C[M,N] = A[M,K] @ B[N,K]^T   (A, B both K-contiguous row-major)
// BM=BN=128, BK=16, 256 threads, 8x8 register tile per thread.
// M,N multiples of 128; K multiple of 16 (true for all our shapes).
// ============================================================================
__global__ __launch_bounds__(256) void sgemm_nt(const float* __restrict__ A,
                                                const float* __restrict__ B,
                                                float* __restrict__ C,
                                                int M, int N, int K) {
    const int BM = 128, BN = 128, BK = 16;
    __shared__ float As[BK][BM];
    __shared__ float Bs[BK][BN];

    int tid = threadIdx.x;
    int bx = blockIdx.x;   // N tile
    int by = blockIdx.y;   // M tile
    int tx = tid & 15;     // 0..15 -> 8 cols each
    int ty = tid >> 4;     // 0..15 -> 8 rows each

    const float* Ab = A + (size_t)by * BM * K;
    const float* Bb = B + (size_t)bx * BN * K;

    float acc[8][8];
#pragma unroll
    for (int i = 0; i < 8; i++)
#pragma unroll
        for (int j = 0; j < 8; j++) acc[i][j] = 0.f;

    for (int k0 = 0; k0 < K; k0 += BK) {
        // Load A-tile and B-tile: each 128 rows x 16 k = 512 float4; 2/thread.
#pragma unroll
        for (int it = 0; it < 2; it++) {
            int idx = tid + it * 256;          // 0..511
            int row = idx >> 2;                // 0..127
            int kk  = (idx & 3) << 2;          // 0,4,8,12
            float4 va = *(const float4*)(Ab + (size_t)row * K + k0 + kk);
            As[kk + 0][row] = va.x; As[kk + 1][row] = va.y;
            As[kk + 2][row] = va.z; As[kk + 3][row] = va.w;
            float4 vb = *(const float4*)(Bb + (size_t)row * K + k0 + kk);
            Bs[kk + 0][row] = vb.x; Bs[kk + 1][row] = vb.y;
            Bs[kk + 2][row] = vb.z; Bs[kk + 3][row] = vb.w;
        }
        __syncthreads();

#pragma unroll
        for (int kk = 0; kk < BK; kk++) {
            float ar[8], br[8];
            float4 a0 = *(const float4*)&As[kk][ty * 8];
            float4 a1 = *(const float4*)&As[kk][ty * 8 + 4];
            ar[0]=a0.x; ar[1]=a0.y; ar[2]=a0.z; ar[3]=a0.w;
            ar[4]=a1.x; ar[5]=a1.y; ar[6]=a1.z; ar[7]=a1.w;
            float4 b0 = *(const float4*)&Bs[kk][tx * 8];
            float4 b1 = *(const float4*)&Bs[kk][tx * 8 + 4];
            br[0]=b0.x; br[1]=b0.y; br[2]=b0.z; br[3]=b0.w;
            br[4]=b1.x; br[5]=b1.y; br[6]=b1.z; br[7]=b1.w;
#pragma unroll
            for (int i = 0; i < 8; i++)
#pragma unroll
                for (int j = 0; j < 8; j++)
                    acc[i][j] = fmaf(ar[i], br[j], acc[i][j]);
        }
        __syncthreads();
    }

    // Store 8x8 as two float4 per row
#pragma unroll
    for (int i = 0; i < 8; i++) {
        float* cp = C + (size_t)(by * BM + ty * 8 + i) * N + bx * BN + tx * 8;
        float4 r0 = make_float4(acc[i][0], acc[i][1], acc[i][2], acc[i][3]);
        float4 r1 = make_float4(acc[i][4], acc[i][5], acc[i][6], acc[i][7]);
        *(float4*)(cp)     = r0;
        *(float4*)(cp + 4) = r1;
    }
}

// ============================================================================
// RoPE applied in-place to Q [S, NH*HD] and K [S, NKV*HD].
// Thread handles one (s, head-slot hh in 0..19, d in 0..63) pair.
//   new[d]    = x[d]*cos[d]       - x[d+64]*sin[d]
//   new[d+64] = x[d+64]*cos[d+64] + x[d]   *sin[d+64]
// ============================================================================
__global__ void rope_kernel(float* __restrict__ Q, float* __restrict__ K,
                            const float* __restrict__ cosp,
                            const float* __restrict__ sinp) {
    int idx = blockIdx.x * blockDim.x + threadIdx.x;
    if (idx >= S_LEN * 20 * 64) return;
    int d  = idx & 63;
    int hh = (idx >> 6) % 20;
    int s  = idx / (64 * 20);

    float c0 = cosp[s * HD + d];
    float c1 = cosp[s * HD + 64 + d];
    float s0 = sinp[s * HD + d];
    float s1 = sinp[s * HD + 64 + d];

    float* base = (hh < NH) ? (Q + (size_t)s * (NH * HD) + hh * HD)
                            : (K + (size_t)s * (NKV * HD) + (hh - NH) * HD);
    float x0 = base[d];
    float x1 = base[d + 64];
    base[d]      = x0 * c0 - x1 * s0;
    base[d + 64] = x1 * c1 + x0 * s1;
}

// ============================================================================
// Block-sparse attention.
// Grid: (T_BLK=64 query blocks, NH=16 heads). 256 threads:
//   thread = (q in 0..63, quarter in 0..3); each thread owns 32 of 128 dims.
// Per selected key block: load K (swizzle-padded smem), partial dots reduced
// across the 4 lanes of a quarter-group via shfl, online softmax, then reuse
// the same smem buffer for V and accumulate.
// Smem row layout: 64 rows x 144 floats; quarter qr at offset qr*36 (4-bank
// skew -> conflict-free 4-address broadcast), float4-aligned (144B steps).
// ============================================================================
__global__ __launch_bounds__(256) void attn_kernel(const float* __restrict__ Q,
                                                   const float* __restrict__ K,
                                                   const float* __restrict__ V,
                                                   float* __restrict__ O) {
    __shared__ float kv_s[B_BLK * 144];
    __shared__ int   sel_s[8];
    __shared__ int   nsel_s;

    int t   = blockIdx.x;
    int h   = blockIdx.y;
    int kvh = h >> 2;              // GQA: 4 q-heads per kv-head
    int tid = threadIdx.x;
    int q   = tid >> 2;            // query row in block
    int qr  = tid & 3;             // dim quarter

    if (tid == 0) {
        int n = 0;
        int lo = (t - 4 > 0) ? (t - 4) : 0;
        int g1 = (t >> 2) << 2;
        int g0 = g1 - 4;
        for (int b = 0; b <= t; b++)
            if (b >= lo || b == g0 || b == g1) sel_s[n++] = b;
        nsel_s = n;
    }

    int srow = t * B_BLK + q;
    float4 qreg[8];
    const float4* qp = (const float4*)(Q + (size_t)srow * (NH * HD) + h * HD + qr * 32);
#pragma unroll
    for (int i = 0; i < 8; i++) qreg[i] = qp[i];

    float o[32];
#pragma unroll
    for (int i = 0; i < 32; i++) o[i] = 0.f;
    float m = -1e30f, l = 0.f;

    __syncthreads();
    int nsel = nsel_s;

    for (int ib = 0; ib < nsel; ib++) {
        int b = sel_s[ib];
        __syncthreads();   // previous V usage of kv_s done

        // ---- load K block (64 x 128) into padded smem ----
#pragma unroll
        for (int it = 0; it < 8; it++) {
            int idx = tid + it * 256;        // 0..2047 float4s
            int r   = idx >> 5;              // row 0..63
            int c4  = idx & 31;              // float4 col
            float4 vv = *(const float4*)(K + (size_t)(b * B_BLK + r) * (NKV * HD)
                                         + kvh * HD + c4 * 4);
            int off = (c4 >> 3) * 36 + (c4 & 7) * 4;
            *(float4*)(&kv_s[r * 144 + off]) = vv;
        }
        __syncthreads();

        // ---- scores ----
        float s[64];
#pragma unroll
        for (int j = 0; j < 64; j++) {
            const float4* kr = (const float4*)(kv_s + j * 144 + qr * 36);
            float a = 0.f;
#pragma unroll
            for (int i = 0; i < 8; i++) {
                float4 kk = kr[i];
                float4 qq = qreg[i];
                a = fmaf(qq.x, kk.x, a);
                a = fmaf(qq.y, kk.y, a);
                a = fmaf(qq.z, kk.z, a);
                a = fmaf(qq.w, kk.w, a);
            }
            a += __shfl_xor_sync(0xffffffffu, a, 1);
            a += __shfl_xor_sync(0xffffffffu, a, 2);
            a *= QK_SCALE;
            if (b == t && j > q) a = NEG_INF;   // causal mask on diagonal block
            s[j] = a;
        }

        // ---- online softmax update ----
        float bmax = -1e30f;
#pragma unroll
        for (int j = 0; j < 64; j++) bmax = fmaxf(bmax, s[j]);
        float newm = fmaxf(m, bmax);
        float corr = __expf(m - newm);
        l *= corr;
#pragma unroll
        for (int i = 0; i < 32; i++) o[i] *= corr;
        float lsum = 0.f;
#pragma unroll
        for (int j = 0; j < 64; j++) {
            s[j] = __expf(s[j] - newm);
            lsum += s[j];
        }
        l += lsum;
        m = newm;

        // ---- load V block into same smem ----
        __syncthreads();
#pragma unroll
        for (int it = 0; it < 8; it++) {
            int idx = tid + it * 256;
            int r   = idx >> 5;
            int c4  = idx & 31;
            float4 vv = *(const float4*)(V + (size_t)(b * B_BLK + r) * (NKV * HD)
                                         + kvh * HD + c4 * 4);
            int off = (c4 >> 3) * 36 + (c4 & 7) * 4;
            *(float4*)(&kv_s[r * 144 + off]) = vv;
        }
        __syncthreads();

        // ---- P @ V ----
#pragma unroll
        for (int j = 0; j < 64; j++) {
            const float4* vr = (const float4*)(kv_s + j * 144 + qr * 36);
            float pj = s[j];
#pragma unroll
            for (int i = 0; i < 8; i++) {
                float4 vv = vr[i];
                o[i * 4 + 0] = fmaf(pj, vv.x, o[i * 4 + 0]);
                o[i * 4 + 1] = fmaf(pj, vv.y, o[i * 4 + 1]);
                o[i * 4 + 2] = fmaf(pj, vv.z, o[i * 4 + 2]);
                o[i * 4 + 3] = fmaf(pj, vv.w, o[i * 4 + 3]);
            }
        }
    }

    float inv = 1.f / l;
    float* op = O + (size_t)srow * (NH * HD) + h * HD + qr * 32;
#pragma unroll
    for (int i = 0; i < 8; i++) {
        float4 r = make_float4(o[i*4+0] * inv, o[i*4+1] * inv,
                               o[i*4+2] * inv, o[i*4+3] * inv);
        *(float4*)(op + i * 4) = r;
    }
}

// ============================================================================
// Launch
// ============================================================================
extern "C" void kernel_launch(void* const* d_in, const int* in_sizes, int n_in,
                              void* d_out, int out_size) {
    (void)in_sizes; (void)n_in; (void)out_size;
    const float* hs   = (const float*)d_in[0];
    const float* cosp = (const float*)d_in[1];
    const float* sinp = (const float*)d_in[2];
    const float* wq   = (const float*)d_in[3];
    const float* wk   = (const float*)d_in[4];
    const float* wv   = (const float*)d_in[5];
    const float* wo   = (const float*)d_in[6];
    float* out = (float*)d_out;

    float *q, *k, *v, *attn;
    cudaGetSymbolAddress((void**)&q,    g_q);
    cudaGetSymbolAddress((void**)&k,    g_k);
    cudaGetSymbolAddress((void**)&v,    g_v);
    cudaGetSymbolAddress((void**)&attn, g_attn);

    // QKV projections
    sgemm_nt<<<dim3(H_DIM / 128, S_LEN / 128), 256>>>(hs, wq, q, S_LEN, NH  * HD, H_DIM);
    sgemm_nt<<<dim3((NKV * HD) / 128, S_LEN / 128), 256>>>(hs, wk, k, S_LEN, NKV * HD, H_DIM);
    sgemm_nt<<<dim3((NKV * HD) / 128, S_LEN / 128), 256>>>(hs, wv, v, S_LEN, NKV * HD, H_DIM);

    // RoPE (Q and K in place)
    rope_kernel<<<(S_LEN * 20 * 64 + 255) / 256, 256>>>(q, k, cosp, sinp);

    // Block-sparse attention
    attn_kernel<<<dim3(T_BLK, NH), 256>>>(q, k, v, attn);

    // Output projection
    sgemm_nt<<<dim3(H_DIM / 128, S_LEN / 128), 256>>>(attn, wo, out, S_LEN, H_DIM, H_DIM);
}

// round 6
// speedup vs baseline: 2.4553x; 2.4553x over previous
#include <cuda_runtime.h>
#include <cuda_fp16.h>
#include <mma.h>
#include <math.h>

#define S_LEN   4096
#define H_DIM   2048
#define NH      16
#define NKV     4
#define HD      128
#define B_BLK   64
#define T_BLK   64
#define NEG_INF (-1e9f)
#define QK_SCALE 0.08838834764831845f

using namespace nvcuda;

// ---------------- scratch (allocation-free) ----------------
__device__ float  g_q[S_LEN * NH * HD];
__device__ float  g_k[S_LEN * NKV * HD];
__device__ float  g_v[S_LEN * NKV * HD];
__device__ float  g_attn[S_LEN * NH * HD];
__device__ __half g_hs_h[S_LEN * H_DIM];
__device__ __half g_wq_h[NH * HD * H_DIM];
__device__ __half g_wk_h[NKV * HD * H_DIM];
__device__ __half g_wv_h[NKV * HD * H_DIM];
__device__ __half g_wo_h[H_DIM * H_DIM];
__device__ __half g_attn_h[S_LEN * H_DIM];

// ---------------- fp32 -> fp16 convert ----------------
__global__ void f2h_kernel(const float4* __restrict__ in, __half2* __restrict__ out, int n4) {
    int i = blockIdx.x * blockDim.x + threadIdx.x;
    if (i < n4) {
        float4 v = in[i];
        out[2 * i]     = __floats2half2_rn(v.x, v.y);
        out[2 * i + 1] = __floats2half2_rn(v.z, v.w);
    }
}

// ============================================================================
// fp16 tensor-core GEMM via WMMA: C[M,N](fp32) = A[M,K] @ B[N,K]^T.
// A, B fp16 row-major (both K-contiguous). Tile 128x128x32, 256 threads.
// 8 warps as 4x2: each warp computes 32 rows x 64 cols = 2x4 wmma 16x16x16.
// Smem rows padded to 40 halfs (80B, multiple of 16B as wmma requires).
// Register-prefetch double buffering (no cp.async, no inline asm).
// Requires M%128==0, N%128==0, K%32==0.
// ============================================================================
#define HG_LDK 40

__global__ __launch_bounds__(256) void hgemm_nt(const __half* __restrict__ A,
                                                const __half* __restrict__ B,
                                                float* __restrict__ C,
                                                int M, int N, int K) {
    __shared__ __half As[128 * HG_LDK];
    __shared__ __half Bs[128 * HG_LDK];

    int tid  = threadIdx.x;
    int bx   = blockIdx.x;   // N tile
    int by   = blockIdx.y;   // M tile
    int warp = tid >> 5;
    int wm   = (warp & 3) * 32;   // warp row offset
    int wn   = (warp >> 2) * 64;  // warp col offset

    const __half* Ab = A + (size_t)by * 128 * K;
    const __half* Bb = B + (size_t)bx * 128 * K;

    wmma::fragment<wmma::accumulator, 16, 16, 16, float> acc[2][4];
    for (int mi = 0; mi < 2; mi++) {
        for (int ni = 0; ni < 4; ni++) {
            wmma::fill_fragment(acc[mi][ni], 0.0f);
        }
    }

    // per-thread load slots: 2 chunks per matrix per stage
    int row0 = tid >> 2;             // 0..63
    int row1 = row0 + 64;            // 64..127
    int seg  = (tid & 3) * 8;        // half offset 0,8,16,24

    const int NKS = K / 32;

    // preload stage 0 into registers
    float4 ra0 = *(const float4*)(Ab + (size_t)row0 * K + seg);
    float4 ra1 = *(const float4*)(Ab + (size_t)row1 * K + seg);
    float4 rb0 = *(const float4*)(Bb + (size_t)row0 * K + seg);
    float4 rb1 = *(const float4*)(Bb + (size_t)row1 * K + seg);

    for (int ks = 0; ks < NKS; ks++) {
        // store prefetched registers to smem
        *(float4*)(As + row0 * HG_LDK + seg) = ra0;
        *(float4*)(As + row1 * HG_LDK + seg) = ra1;
        *(float4*)(Bs + row0 * HG_LDK + seg) = rb0;
        *(float4*)(Bs + row1 * HG_LDK + seg) = rb1;
        __syncthreads();

        // prefetch next stage from global
        if (ks + 1 < NKS) {
            int k0 = (ks + 1) * 32;
            ra0 = *(const float4*)(Ab + (size_t)row0 * K + k0 + seg);
            ra1 = *(const float4*)(Ab + (size_t)row1 * K + k0 + seg);
            rb0 = *(const float4*)(Bb + (size_t)row0 * K + k0 + seg);
            rb1 = *(const float4*)(Bb + (size_t)row1 * K + k0 + seg);
        }

        // compute on smem tile
        for (int kc = 0; kc < 2; kc++) {
            wmma::fragment<wmma::matrix_a, 16, 16, 16, __half, wmma::row_major> af[2];
            wmma::fragment<wmma::matrix_b, 16, 16, 16, __half, wmma::col_major> bf[4];
            for (int mi = 0; mi < 2; mi++) {
                wmma::load_matrix_sync(af[mi], As + (wm + mi * 16) * HG_LDK + kc * 16, HG_LDK);
            }
            for (int ni = 0; ni < 4; ni++) {
                wmma::load_matrix_sync(bf[ni], Bs + (wn + ni * 16) * HG_LDK + kc * 16, HG_LDK);
            }
            for (int mi = 0; mi < 2; mi++) {
                for (int ni = 0; ni < 4; ni++) {
                    wmma::mma_sync(acc[mi][ni], af[mi], bf[ni], acc[mi][ni]);
                }
            }
        }
        __syncthreads();
    }

    for (int mi = 0; mi < 2; mi++) {
        for (int ni = 0; ni < 4; ni++) {
            float* cp = C + (size_t)(by * 128 + wm + mi * 16) * N + bx * 128 + wn + ni * 16;
            wmma::store_matrix_sync(cp, acc[mi][ni], N, wmma::mem_row_major);
        }
    }
}

// ============================================================================
// RoPE in-place on Q [S, NH*HD] and K [S, NKV*HD]
// ============================================================================
__global__ void rope_kernel(float* __restrict__ Q, float* __restrict__ K,
                            const float* __restrict__ cosp,
                            const float* __restrict__ sinp) {
    int idx = blockIdx.x * blockDim.x + threadIdx.x;
    if (idx >= S_LEN * 20 * 64) return;
    int d  = idx & 63;
    int hh = (idx >> 6) % 20;
    int s  = idx / (64 * 20);

    float c0 = cosp[s * HD + d];
    float c1 = cosp[s * HD + 64 + d];
    float s0 = sinp[s * HD + d];
    float s1 = sinp[s * HD + 64 + d];

    float* base = (hh < NH) ? (Q + (size_t)s * (NH * HD) + hh * HD)
                            : (K + (size_t)s * (NKV * HD) + (hh - NH) * HD);
    float x0 = base[d];
    float x1 = base[d + 64];
    base[d]      = x0 * c0 - x1 * s0;
    base[d + 64] = x1 * c1 + x0 * s1;
}

// ============================================================================
// Block-sparse attention (fp32), unchanged from round 1 (known good).
// ============================================================================
__global__ __launch_bounds__(256) void attn_kernel(const float* __restrict__ Q,
                                                   const float* __restrict__ K,
                                                   const float* __restrict__ V,
                                                   float* __restrict__ O) {
    __shared__ float kv_s[B_BLK * 144];
    __shared__ int   sel_s[8];
    __shared__ int   nsel_s;

    int t   = blockIdx.x;
    int h   = blockIdx.y;
    int kvh = h >> 2;
    int tid = threadIdx.x;
    int q   = tid >> 2;
    int qr  = tid & 3;

    if (tid == 0) {
        int n = 0;
        int lo = (t - 4 > 0) ? (t - 4) : 0;
        int g1 = (t >> 2) << 2;
        int g0 = g1 - 4;
        for (int b = 0; b <= t; b++) {
            if (b >= lo || b == g0 || b == g1) sel_s[n++] = b;
        }
        nsel_s = n;
    }

    int srow = t * B_BLK + q;
    float4 qreg[8];
    const float4* qp = (const float4*)(Q + (size_t)srow * (NH * HD) + h * HD + qr * 32);
#pragma unroll
    for (int i = 0; i < 8; i++) qreg[i] = qp[i];

    float o[32];
#pragma unroll
    for (int i = 0; i < 32; i++) o[i] = 0.f;
    float m = -1e30f, l = 0.f;

    __syncthreads();
    int nsel = nsel_s;

    for (int ib = 0; ib < nsel; ib++) {
        int b = sel_s[ib];
        __syncthreads();

#pragma unroll
        for (int it = 0; it < 8; it++) {
            int idx = tid + it * 256;
            int r   = idx >> 5;
            int c4  = idx & 31;
            float4 vv = *(const float4*)(K + (size_t)(b * B_BLK + r) * (NKV * HD)
                                         + kvh * HD + c4 * 4);
            int off = (c4 >> 3) * 36 + (c4 & 7) * 4;
            *(float4*)(&kv_s[r * 144 + off]) = vv;
        }
        __syncthreads();

        float s[64];
#pragma unroll
        for (int j = 0; j < 64; j++) {
            const float4* kr = (const float4*)(kv_s + j * 144 + qr * 36);
            float a = 0.f;
#pragma unroll
            for (int i = 0; i < 8; i++) {
                float4 kk = kr[i];
                float4 qq = qreg[i];
                a = fmaf(qq.x, kk.x, a);
                a = fmaf(qq.y, kk.y, a);
                a = fmaf(qq.z, kk.z, a);
                a = fmaf(qq.w, kk.w, a);
            }
            a += __shfl_xor_sync(0xffffffffu, a, 1);
            a += __shfl_xor_sync(0xffffffffu, a, 2);
            a *= QK_SCALE;
            if (b == t && j > q) a = NEG_INF;
            s[j] = a;
        }

        float bmax = -1e30f;
#pragma unroll
        for (int j = 0; j < 64; j++) bmax = fmaxf(bmax, s[j]);
        float newm = fmaxf(m, bmax);
        float corr = __expf(m - newm);
        l *= corr;
#pragma unroll
        for (int i = 0; i < 32; i++) o[i] *= corr;
        float lsum = 0.f;
#pragma unroll
        for (int j = 0; j < 64; j++) {
            s[j] = __expf(s[j] - newm);
            lsum += s[j];
        }
        l += lsum;
        m = newm;

        __syncthreads();
#pragma unroll
        for (int it = 0; it < 8; it++) {
            int idx = tid + it * 256;
            int r   = idx >> 5;
            int c4  = idx & 31;
            float4 vv = *(const float4*)(V + (size_t)(b * B_BLK + r) * (NKV * HD)
                                         + kvh * HD + c4 * 4);
            int off = (c4 >> 3) * 36 + (c4 & 7) * 4;
            *(float4*)(&kv_s[r * 144 + off]) = vv;
        }
        __syncthreads();

#pragma unroll
        for (int j = 0; j < 64; j++) {
            const float4* vr = (const float4*)(kv_s + j * 144 + qr * 36);
            float pj = s[j];
#pragma unroll
            for (int i = 0; i < 8; i++) {
                float4 vv = vr[i];
                o[i * 4 + 0] = fmaf(pj, vv.x, o[i * 4 + 0]);
                o[i * 4 + 1] = fmaf(pj, vv.y, o[i * 4 + 1]);
                o[i * 4 + 2] = fmaf(pj, vv.z, o[i * 4 + 2]);
                o[i * 4 + 3] = fmaf(pj, vv.w, o[i * 4 + 3]);
            }
        }
    }

    float inv = 1.f / l;
    float* op = O + (size_t)srow * (NH * HD) + h * HD + qr * 32;
#pragma unroll
    for (int i = 0; i < 8; i++) {
        float4 r = make_float4(o[i*4+0] * inv, o[i*4+1] * inv,
                               o[i*4+2] * inv, o[i*4+3] * inv);
        *(float4*)(op + i * 4) = r;
    }
}

// ============================================================================
// Launch
// ============================================================================
extern "C" void kernel_launch(void* const* d_in, const int* in_sizes, int n_in,
                              void* d_out, int out_size) {
    (void)in_sizes; (void)n_in; (void)out_size;
    const float* hs   = (const float*)d_in[0];
    const float* cosp = (const float*)d_in[1];
    const float* sinp = (const float*)d_in[2];
    const float* wq   = (const float*)d_in[3];
    const float* wk   = (const float*)d_in[4];
    const float* wv   = (const float*)d_in[5];
    const float* wo   = (const float*)d_in[6];
    float* out = (float*)d_out;

    float* q;
    float* k;
    float* v;
    float* attn;
    __half* hs_h;
    __half* wq_h;
    __half* wk_h;
    __half* wv_h;
    __half* wo_h;
    __half* attn_h;
    cudaGetSymbolAddress((void**)&q,      g_q);
    cudaGetSymbolAddress((void**)&k,      g_k);
    cudaGetSymbolAddress((void**)&v,      g_v);
    cudaGetSymbolAddress((void**)&attn,   g_attn);
    cudaGetSymbolAddress((void**)&hs_h,   g_hs_h);
    cudaGetSymbolAddress((void**)&wq_h,   g_wq_h);
    cudaGetSymbolAddress((void**)&wk_h,   g_wk_h);
    cudaGetSymbolAddress((void**)&wv_h,   g_wv_h);
    cudaGetSymbolAddress((void**)&wo_h,   g_wo_h);
    cudaGetSymbolAddress((void**)&attn_h, g_attn_h);

    const int TPB = 256;
    int n4;

    n4 = S_LEN * H_DIM / 4;
    f2h_kernel<<<(n4 + TPB - 1) / TPB, TPB>>>((const float4*)hs, (__half2*)hs_h, n4);
    n4 = NH * HD * H_DIM / 4;
    f2h_kernel<<<(n4 + TPB - 1) / TPB, TPB>>>((const float4*)wq, (__half2*)wq_h, n4);
    n4 = NKV * HD * H_DIM / 4;
    f2h_kernel<<<(n4 + TPB - 1) / TPB, TPB>>>((const float4*)wk, (__half2*)wk_h, n4);
    f2h_kernel<<<(n4 + TPB - 1) / TPB, TPB>>>((const float4*)wv, (__half2*)wv_h, n4);
    n4 = H_DIM * H_DIM / 4;
    f2h_kernel<<<(n4 + TPB - 1) / TPB, TPB>>>((const float4*)wo, (__half2*)wo_h, n4);

    hgemm_nt<<<dim3((NH * HD) / 128, S_LEN / 128), 256>>>(hs_h, wq_h, q, S_LEN, NH * HD, H_DIM);
    hgemm_nt<<<dim3((NKV * HD) / 128, S_LEN / 128), 256>>>(hs_h, wk_h, k, S_LEN, NKV * HD, H_DIM);
    hgemm_nt<<<dim3((NKV * HD) / 128, S_LEN / 128), 256>>>(hs_h, wv_h, v, S_LEN, NKV * HD, H_DIM);

    rope_kernel<<<(S_LEN * 20 * 64 + TPB - 1) / TPB, TPB>>>(q, k, cosp, sinp);

    attn_kernel<<<dim3(T_BLK, NH), 256>>>(q, k, v, attn);

    n4 = S_LEN * H_DIM / 4;
    f2h_kernel<<<(n4 + TPB - 1) / TPB, TPB>>>((const float4*)attn, (__half2*)attn_h, n4);
    hgemm_nt<<<dim3(H_DIM / 128, S_LEN / 128), 256>>>(attn_h, wo_h, out, S_LEN, H_DIM, H_DIM);
}

// round 7
// speedup vs baseline: 4.9868x; 2.0311x over previous
#include <cuda_runtime.h>
#include <cuda_fp16.h>
#include <cuda_pipeline.h>
#include <mma.h>
#include <math.h>

#define S_LEN   4096
#define H_DIM   2048
#define NH      16
#define NKV     4
#define HD      128
#define B_BLK   64
#define T_BLK   64
#define QK_SCALE 0.08838834764831845f

using namespace nvcuda;

// ---------------- scratch (allocation-free) ----------------
__device__ float  g_q[S_LEN * NH * HD];
__device__ float  g_k[S_LEN * NKV * HD];
__device__ float  g_v[S_LEN * NKV * HD];
__device__ __half g_qh[S_LEN * NH * HD];
__device__ __half g_kh[S_LEN * NKV * HD];
__device__ __half g_vh[S_LEN * NKV * HD];
__device__ __half g_hs_h[S_LEN * H_DIM];
__device__ __half g_wq_h[NH * HD * H_DIM];
__device__ __half g_wk_h[NKV * HD * H_DIM];
__device__ __half g_wv_h[NKV * HD * H_DIM];
__device__ __half g_wo_h[H_DIM * H_DIM];
__device__ __half g_attn_h[S_LEN * H_DIM];

// ---------------- fp32 -> fp16 convert ----------------
__global__ void f2h_kernel(const float4* __restrict__ in, __half2* __restrict__ out, int n4) {
    int i = blockIdx.x * blockDim.x + threadIdx.x;
    if (i < n4) {
        float4 v = in[i];
        out[2 * i]     = __floats2half2_rn(v.x, v.y);
        out[2 * i + 1] = __floats2half2_rn(v.z, v.w);
    }
}

// ============================================================================
// fp16 WMMA GEMM: C[M,N](fp32) = A[M,K] @ B[N,K]^T, async double-buffered.
// Tile 128x128x32, 256 threads, 8 warps as 4x2 (32x64 warp tiles).
// ============================================================================
#define HG_LDK 40

__device__ __forceinline__ void hg_load_stage(const __half* Ab, const __half* Bb,
                                              int K, int k0, int tid,
                                              __half* As, __half* Bs) {
    for (int it = 0; it < 2; it++) {
        int idx = tid + it * 256;     // 0..511
        int row = idx >> 2;           // 0..127
        int seg = (idx & 3) * 8;      // half offset 0,8,16,24
        __pipeline_memcpy_async(As + row * HG_LDK + seg, Ab + (size_t)row * K + k0 + seg, 16);
        __pipeline_memcpy_async(Bs + row * HG_LDK + seg, Bb + (size_t)row * K + k0 + seg, 16);
    }
}

__global__ __launch_bounds__(256) void hgemm_nt(const __half* __restrict__ A,
                                                const __half* __restrict__ B,
                                                float* __restrict__ C,
                                                int M, int N, int K) {
    __shared__ __half As[2][128 * HG_LDK];
    __shared__ __half Bs[2][128 * HG_LDK];

    int tid  = threadIdx.x;
    int bx   = blockIdx.x;
    int by   = blockIdx.y;
    int warp = tid >> 5;
    int wm   = (warp & 3) * 32;
    int wn   = (warp >> 2) * 64;

    const __half* Ab = A + (size_t)by * 128 * K;
    const __half* Bb = B + (size_t)bx * 128 * K;

    wmma::fragment<wmma::accumulator, 16, 16, 16, float> acc[2][4];
    for (int mi = 0; mi < 2; mi++) {
        for (int ni = 0; ni < 4; ni++) {
            wmma::fill_fragment(acc[mi][ni], 0.0f);
        }
    }

    const int NKS = K / 32;

    hg_load_stage(Ab, Bb, K, 0, tid, As[0], Bs[0]);
    __pipeline_commit();

    for (int ks = 0; ks < NKS; ks++) {
        if (ks + 1 < NKS) {
            int nb = (ks + 1) & 1;
            hg_load_stage(Ab, Bb, K, (ks + 1) * 32, tid, As[nb], Bs[nb]);
            __pipeline_commit();
            __pipeline_wait_prior(1);
        } else {
            __pipeline_wait_prior(0);
        }
        __syncthreads();

        int buf = ks & 1;
        for (int kc = 0; kc < 2; kc++) {
            wmma::fragment<wmma::matrix_a, 16, 16, 16, __half, wmma::row_major> af[2];
            wmma::fragment<wmma::matrix_b, 16, 16, 16, __half, wmma::col_major> bf[4];
            for (int mi = 0; mi < 2; mi++) {
                wmma::load_matrix_sync(af[mi], As[buf] + (wm + mi * 16) * HG_LDK + kc * 16, HG_LDK);
            }
            for (int ni = 0; ni < 4; ni++) {
                wmma::load_matrix_sync(bf[ni], Bs[buf] + (wn + ni * 16) * HG_LDK + kc * 16, HG_LDK);
            }
            for (int mi = 0; mi < 2; mi++) {
                for (int ni = 0; ni < 4; ni++) {
                    wmma::mma_sync(acc[mi][ni], af[mi], bf[ni], acc[mi][ni]);
                }
            }
        }
        __syncthreads();
    }

    for (int mi = 0; mi < 2; mi++) {
        for (int ni = 0; ni < 4; ni++) {
            float* cp = C + (size_t)(by * 128 + wm + mi * 16) * N + bx * 128 + wn + ni * 16;
            wmma::store_matrix_sync(cp, acc[mi][ni], N, wmma::mem_row_major);
        }
    }
}

// ============================================================================
// RoPE: reads fp32 Q/K, writes fp16 Q/K.
// ============================================================================
__global__ void rope_h_kernel(const float* __restrict__ Q, const float* __restrict__ K,
                              const float* __restrict__ cosp, const float* __restrict__ sinp,
                              __half* __restrict__ Qh, __half* __restrict__ Kh) {
    int idx = blockIdx.x * blockDim.x + threadIdx.x;
    if (idx >= S_LEN * 20 * 64) return;
    int d  = idx & 63;
    int hh = (idx >> 6) % 20;
    int s  = idx / (64 * 20);

    float c0 = cosp[s * HD + d];
    float c1 = cosp[s * HD + 64 + d];
    float s0 = sinp[s * HD + d];
    float s1 = sinp[s * HD + 64 + d];

    const float* base;
    __half* baseh;
    if (hh < NH) {
        base  = Q  + (size_t)s * (NH * HD) + hh * HD;
        baseh = Qh + (size_t)s * (NH * HD) + hh * HD;
    } else {
        base  = K  + (size_t)s * (NKV * HD) + (hh - NH) * HD;
        baseh = Kh + (size_t)s * (NKV * HD) + (hh - NH) * HD;
    }
    float x0 = base[d];
    float x1 = base[d + 64];
    baseh[d]      = __float2half(x0 * c0 - x1 * s0);
    baseh[d + 64] = __float2half(x1 * c1 + x0 * s1);
}

// ============================================================================
// Tensor-core block-sparse flash attention.
// One CTA per (t, h). 256 threads = 8 warps (4 row-groups x 2 col-groups).
// Dynamic smem layout (bytes):
//   [0,      17408)  sQ  : 64 x 136 half
//   [17408,  34816)  sS  : 64 x 68 float   (aliased with sP: 64 x 136 half)
//   [34816,  52224)  sKV : 64 x 136 half   (K, then V)
//   [52224,  84992)  sO  : 64 x 128 float
// ============================================================================
#define AT_SMEM_BYTES 84992
#define AT_LDH 136

__global__ __launch_bounds__(256) void attn_wmma(const __half* __restrict__ Qh,
                                                 const __half* __restrict__ Kh,
                                                 const __half* __restrict__ Vh,
                                                 __half* __restrict__ Oh) {
    extern __shared__ char smraw[];
    __half* sQ  = (__half*)(smraw);
    float*  sS  = (float*)(smraw + 17408);
    __half* sP  = (__half*)(smraw + 17408);
    __half* sKV = (__half*)(smraw + 34816);
    float*  sO  = (float*)(smraw + 52224);
    __shared__ float sM[64];
    __shared__ float sL[64];
    __shared__ float sCorr[64];
    __shared__ int   sel_s[8];
    __shared__ int   nsel_s;

    int t   = blockIdx.x;
    int h   = blockIdx.y;
    int kvh = h >> 2;
    int tid = threadIdx.x;
    int w   = tid >> 5;
    int wm  = (w & 3) * 16;     // warp row base (S and PV)
    int wn  = (w >> 2) * 32;    // warp col base for S (2 tiles)
    int wn2 = (w >> 2) * 64;    // warp col base for PV (4 tiles)
    int r   = tid >> 2;         // row 0..63 (softmax phases)
    int q4  = tid & 3;          // quad lane
    int c0  = q4 * 16;

    if (tid == 0) {
        int n = 0;
        int lo = (t - 4 > 0) ? (t - 4) : 0;
        int g1 = (t >> 2) << 2;
        int g0 = g1 - 4;
        for (int b = 0; b <= t; b++) {
            if (b >= lo || b == g0 || b == g1) sel_s[n++] = b;
        }
        nsel_s = n;
    }

    // load Q tile: 64 x 128 fp16
    for (int it = 0; it < 4; it++) {
        int idx = tid + it * 256;          // 0..1023
        int rr  = idx >> 4;                // 0..63
        int cc  = (idx & 15) * 8;          // half offset
        *(float4*)(sQ + rr * AT_LDH + cc) =
            *(const float4*)(Qh + ((size_t)(t * 64 + rr) * NH + h) * HD + cc);
    }
    for (int i = tid; i < 64 * 128; i += 256) sO[i] = 0.f;
    if (tid < 64) { sM[tid] = -1e30f; sL[tid] = 0.f; }
    __syncthreads();
    int nsel = nsel_s;

    for (int ib = 0; ib < nsel; ib++) {
        int b = sel_s[ib];
        bool diag = (b == t);

        // ---- load K block ----
        for (int it = 0; it < 4; it++) {
            int idx = tid + it * 256;
            int rr  = idx >> 4;
            int cc  = (idx & 15) * 8;
            *(float4*)(sKV + rr * AT_LDH + cc) =
                *(const float4*)(Kh + ((size_t)(b * 64 + rr) * NKV + kvh) * HD + cc);
        }
        __syncthreads();

        // ---- S = Q @ K^T (per warp: 16 rows x 32 cols) ----
        {
            wmma::fragment<wmma::accumulator, 16, 16, 16, float> sc[2];
            wmma::fill_fragment(sc[0], 0.0f);
            wmma::fill_fragment(sc[1], 0.0f);
            for (int kk = 0; kk < 8; kk++) {
                wmma::fragment<wmma::matrix_a, 16, 16, 16, __half, wmma::row_major> aq;
                wmma::load_matrix_sync(aq, sQ + wm * AT_LDH + kk * 16, AT_LDH);
                for (int nt = 0; nt < 2; nt++) {
                    wmma::fragment<wmma::matrix_b, 16, 16, 16, __half, wmma::col_major> bk;
                    wmma::load_matrix_sync(bk, sKV + (wn + nt * 16) * AT_LDH + kk * 16, AT_LDH);
                    wmma::mma_sync(sc[nt], aq, bk, sc[nt]);
                }
            }
            wmma::store_matrix_sync(sS + wm * 68 + wn,      sc[0], 68, wmma::mem_row_major);
            wmma::store_matrix_sync(sS + wm * 68 + wn + 16, sc[1], 68, wmma::mem_row_major);
        }
        __syncthreads();

        // ---- row max + correction (4 threads per row) ----
        {
            float mx = -1e30f;
            for (int i = 0; i < 16; i++) {
                int c = c0 + i;
                float sv = sS[r * 68 + c] * QK_SCALE;
                if (diag && c > r) sv = -1e30f;
                mx = fmaxf(mx, sv);
            }
            mx = fmaxf(mx, __shfl_xor_sync(0xffffffffu, mx, 1));
            mx = fmaxf(mx, __shfl_xor_sync(0xffffffffu, mx, 2));
            if (q4 == 0) {
                float nm = fmaxf(sM[r], mx);
                sCorr[r] = __expf(sM[r] - nm);
                sM[r] = nm;
            }
        }
        __syncthreads();

        // ---- exp to registers; then write P (fp16, aliases sS) + rescale O ----
        float pv[16];
        {
            float nm = sM[r];
            for (int i = 0; i < 16; i++) {
                int c = c0 + i;
                float sv = sS[r * 68 + c] * QK_SCALE;
                pv[i] = (diag && c > r) ? 0.f : __expf(sv - nm);
            }
        }
        float corr_r = sCorr[r];
        __syncthreads();   // all S reads done before aliased P writes
        for (int i = 0; i < 16; i += 2) {
            *(__half2*)(sP + r * AT_LDH + c0 + i) = __floats2half2_rn(pv[i], pv[i + 1]);
        }
        {
            float* orow = sO + r * 128 + q4 * 32;
            for (int i = 0; i < 32; i++) orow[i] *= corr_r;
        }
        // l update from registers
        {
            float ls = 0.f;
            for (int i = 0; i < 16; i++) ls += pv[i];
            ls += __shfl_xor_sync(0xffffffffu, ls, 1);
            ls += __shfl_xor_sync(0xffffffffu, ls, 2);
            if (q4 == 0) sL[r] = sL[r] * corr_r + ls;
        }
        // ---- load V block (sKV free: K last read before prior sync) ----
        for (int it = 0; it < 4; it++) {
            int idx = tid + it * 256;
            int rr  = idx >> 4;
            int cc  = (idx & 15) * 8;
            *(float4*)(sKV + rr * AT_LDH + cc) =
                *(const float4*)(Vh + ((size_t)(b * 64 + rr) * NKV + kvh) * HD + cc);
        }
        __syncthreads();

        // ---- O += P @ V (per warp: 16 rows x 64 cols) ----
        {
            wmma::fragment<wmma::matrix_a, 16, 16, 16, __half, wmma::row_major> ap[4];
            for (int kk = 0; kk < 4; kk++) {
                wmma::load_matrix_sync(ap[kk], sP + wm * AT_LDH + kk * 16, AT_LDH);
            }
            for (int nt = 0; nt < 4; nt++) {
                wmma::fragment<wmma::accumulator, 16, 16, 16, float> oacc;
                wmma::load_matrix_sync(oacc, sO + wm * 128 + wn2 + nt * 16, 128, wmma::mem_row_major);
                for (int kk = 0; kk < 4; kk++) {
                    wmma::fragment<wmma::matrix_b, 16, 16, 16, __half, wmma::row_major> bv;
                    wmma::load_matrix_sync(bv, sKV + kk * 16 * AT_LDH + wn2 + nt * 16, AT_LDH);
                    wmma::mma_sync(oacc, ap[kk], bv, oacc);
                }
                wmma::store_matrix_sync(sO + wm * 128 + wn2 + nt * 16, oacc, 128, wmma::mem_row_major);
            }
        }
        __syncthreads();
    }

    // ---- normalize + write fp16 output ----
    {
        float inv = 1.f / sL[r];
        const float* orow = sO + r * 128 + q4 * 32;
        __half2* dst = (__half2*)(Oh + ((size_t)(t * 64 + r) * NH + h) * HD + q4 * 32);
        for (int i = 0; i < 32; i += 2) {
            dst[i >> 1] = __floats2half2_rn(orow[i] * inv, orow[i + 1] * inv);
        }
    }
}

// ============================================================================
// Launch
// ============================================================================
extern "C" void kernel_launch(void* const* d_in, const int* in_sizes, int n_in,
                              void* d_out, int out_size) {
    (void)in_sizes; (void)n_in; (void)out_size;
    const float* hs   = (const float*)d_in[0];
    const float* cosp = (const float*)d_in[1];
    const float* sinp = (const float*)d_in[2];
    const float* wq   = (const float*)d_in[3];
    const float* wk   = (const float*)d_in[4];
    const float* wv   = (const float*)d_in[5];
    const float* wo   = (const float*)d_in[6];
    float* out = (float*)d_out;

    float* q;
    float* k;
    float* v;
    __half* qh;
    __half* kh;
    __half* vh;
    __half* hs_h;
    __half* wq_h;
    __half* wk_h;
    __half* wv_h;
    __half* wo_h;
    __half* attn_h;
    cudaGetSymbolAddress((void**)&q,      g_q);
    cudaGetSymbolAddress((void**)&k,      g_k);
    cudaGetSymbolAddress((void**)&v,      g_v);
    cudaGetSymbolAddress((void**)&qh,     g_qh);
    cudaGetSymbolAddress((void**)&kh,     g_kh);
    cudaGetSymbolAddress((void**)&vh,     g_vh);
    cudaGetSymbolAddress((void**)&hs_h,   g_hs_h);
    cudaGetSymbolAddress((void**)&wq_h,   g_wq_h);
    cudaGetSymbolAddress((void**)&wk_h,   g_wk_h);
    cudaGetSymbolAddress((void**)&wv_h,   g_wv_h);
    cudaGetSymbolAddress((void**)&wo_h,   g_wo_h);
    cudaGetSymbolAddress((void**)&attn_h, g_attn_h);

    cudaFuncSetAttribute(attn_wmma, cudaFuncAttributeMaxDynamicSharedMemorySize, AT_SMEM_BYTES);

    const int TPB = 256;
    int n4;

    n4 = S_LEN * H_DIM / 4;
    f2h_kernel<<<(n4 + TPB - 1) / TPB, TPB>>>((const float4*)hs, (__half2*)hs_h, n4);
    n4 = NH * HD * H_DIM / 4;
    f2h_kernel<<<(n4 + TPB - 1) / TPB, TPB>>>((const float4*)wq, (__half2*)wq_h, n4);
    n4 = NKV * HD * H_DIM / 4;
    f2h_kernel<<<(n4 + TPB - 1) / TPB, TPB>>>((const float4*)wk, (__half2*)wk_h, n4);
    f2h_kernel<<<(n4 + TPB - 1) / TPB, TPB>>>((const float4*)wv, (__half2*)wv_h, n4);
    n4 = H_DIM * H_DIM / 4;
    f2h_kernel<<<(n4 + TPB - 1) / TPB, TPB>>>((const float4*)wo, (__half2*)wo_h, n4);

    hgemm_nt<<<dim3((NH * HD) / 128, S_LEN / 128), 256>>>(hs_h, wq_h, q, S_LEN, NH * HD, H_DIM);
    hgemm_nt<<<dim3((NKV * HD) / 128, S_LEN / 128), 256>>>(hs_h, wk_h, k, S_LEN, NKV * HD, H_DIM);
    hgemm_nt<<<dim3((NKV * HD) / 128, S_LEN / 128), 256>>>(hs_h, wv_h, v, S_LEN, NKV * HD, H_DIM);

    rope_h_kernel<<<(S_LEN * 20 * 64 + TPB - 1) / TPB, TPB>>>(q, k, cosp, sinp, qh, kh);
    n4 = S_LEN * NKV * HD / 4;
    f2h_kernel<<<(n4 + TPB - 1) / TPB, TPB>>>((const float4*)v, (__half2*)vh, n4);

    attn_wmma<<<dim3(T_BLK, NH), 256, AT_SMEM_BYTES>>>(qh, kh, vh, attn_h);

    hgemm_nt<<<dim3(H_DIM / 128, S_LEN / 128), 256>>>(attn_h, wo_h, out, S_LEN, H_DIM, H_DIM);
}